// round 15
// baseline (speedup 1.0000x reference)
#include <cuda_runtime.h>
#include <cstdint>
#include <cstddef>

#define DIM      900
#define TLEN     31000
#define DISCARD  1000
#define OUTCOLS  29999      /* TLEN - DISCARD - 1 */
#define NCTA     30
#define RPC      30         /* rows per CTA */
#define NTHREADS 512        /* 16 warps; warps 0-14: 2 rows, warp 15: 0 rows */
#define PADDIM   1024

// Broadcast state: 900 self-verifying 8B words {f32 value (lo), u32 tag (hi)},
// ping-pong by step parity. 64-bit aligned stores are single-copy atomic: a
// fresh tag ALWAYS travels with its fresh value — no fences, no flags.
// Lap safety: a row's tag on parity p advances +2 only after every CTA's poll
// warps consumed the previous tag on that parity (bar1 couples all 16 chunks
// of a CTA => all 900 rows). Tags grow monotonically across graph replays;
// base is recovered from g_xp[1][0], which cannot be overwritten before all
// warps read it (overwrite needs a step-1 publish => all step-0 publishes =>
// all base reads done).
__device__ __align__(16) unsigned long long g_xp[2][PADDIM];

__device__ __forceinline__ ulonglong2 ld_cv2(const unsigned long long* p) {
    ulonglong2 v;
    asm volatile("ld.global.cv.v2.b64 {%0,%1}, [%2];"
                 : "=l"(v.x), "=l"(v.y) : "l"(p) : "memory");
    return v;
}
__device__ __forceinline__ void st_cg64(unsigned long long* p, unsigned long long v) {
    asm volatile("st.global.cg.b64 [%0], %1;" :: "l"(p), "l"(v) : "memory");
}
__device__ __forceinline__ unsigned long long pk_pair(float v, unsigned tag) {
    unsigned long long r;
    asm("mov.b64 %0, {%1,%2};" : "=l"(r) : "r"(__float_as_uint(v)), "r"(tag));
    return r;
}
__device__ __forceinline__ void unpk(unsigned long long w, unsigned& lo, unsigned& hi) {
    asm("mov.b64 {%0,%1}, %2;" : "=r"(lo), "=r"(hi) : "l"(w));
}
__device__ __forceinline__ unsigned long long pk2(float a, float b) {
    unsigned long long r;
    asm("mov.b64 %0, {%1,%2};" : "=l"(r) : "f"(a), "f"(b));
    return r;
}
// Packed dual fp32 FMA / ADD (B300 f32x2 pipe) — exact fp32 semantics.
__device__ __forceinline__ void fma2(unsigned long long& acc,
                                     unsigned long long a, unsigned long long b) {
    asm("fma.rn.f32x2 %0, %1, %2, %0;" : "+l"(acc) : "l"(a), "l"(b));
}
__device__ __forceinline__ unsigned long long add2(unsigned long long a,
                                                   unsigned long long b) {
    unsigned long long r;
    asm("add.rn.f32x2 %0, %1, %2;" : "=l"(r) : "l"(a), "l"(b));
    return r;
}
__device__ __forceinline__ float sum2(unsigned long long a) {
    float lo, hi;
    asm("mov.b64 {%0,%1}, %2;" : "=f"(lo), "=f"(hi) : "l"(a));
    return lo + hi;
}
__device__ __forceinline__ void unpkf(unsigned long long w, float& lo, float& hi) {
    asm("mov.b64 {%0,%1}, %2;" : "=f"(lo), "=f"(hi) : "l"(w));
}
// Fast tanh: 1 - 2/(exp(2x)+1). MUFU-based; ~1e-7 abs error.
__device__ __forceinline__ float ftanh(float x) {
    float e = __expf(2.0f * x);
    return 1.0f - __fdividef(2.0f, e + 1.0f);
}

__global__ void __launch_bounds__(NTHREADS, 1) esn_persistent(
    const float* __restrict__ W,     // (900, 900) row-major, symmetric
    const float* __restrict__ Win,   // (900, 900) row-major; column 0 used
    const float* __restrict__ u,     // (31000,)
    float* __restrict__ out)         // (900, 29999) row-major
{
    __shared__ __align__(16) float x_sm[PADDIM];   // single buffer, 2 bars (R13)

    const int tid  = threadIdx.x;
    const int cta  = blockIdx.x;
    const int warp = tid >> 5;
    const int lane = tid & 31;

    // Zero x_sm; pad region [900,1024) stays zero forever.
    for (int i = tid; i < PADDIM; i += NTHREADS) x_sm[i] = 0.0f;

    // Launch base: tag of row 0, parity 1 (last parity a full launch writes).
    unsigned base;
    { unsigned lo; unpk(ld_cv2(&g_xp[1][0]).x, lo, base); }

    // ---- This warp's 2 rows of W into registers, pre-scaled by 0.9 ----
    const int rbase = cta * RPC + warp * 2;
    unsigned long long wp[2][8][2];
    #pragma unroll
    for (int g = 0; g < 2; ++g) {
        const bool vg = (warp * 2 + g) < RPC;   // warp 15: no rows
        #pragma unroll
        for (int k = 0; k < 8; ++k) {
            const int col = k * 128 + lane * 4;
            float a0 = 0.f, a1 = 0.f, a2 = 0.f, a3 = 0.f;
            if (vg && col + 3 < DIM) {
                float4 v = *(const float4*)(W + (size_t)(rbase + g) * DIM + col);
                a0 = v.x; a1 = v.y; a2 = v.z; a3 = v.w;
            }
            wp[g][k][0] = pk2(0.9f * a0, 0.9f * a1);
            wp[g][k][1] = pk2(0.9f * a2, 0.9f * a3);
        }
    }
    const int  myg   = lane >> 4;                  // 0: lanes 0-15, 1: 16-31
    const bool vrow  = (warp * 2 + myg) < RPC;
    const int  myrow = rbase + myg;
    const float winv = vrow ? Win[(size_t)myrow * DIM] : 0.0f;   // W_in[row,0]
    const bool winj  = ((lane & 15) == 0);   // lanes 0 / 16 inject + publish

    // Poll chunk: pairs [warp*64 + lane*2, +2) — ONE 16B load per lane.
    // Warps 0-13 fully active; warp 14: lanes 0-1; warp 15: inactive.
    // Inactive lanes contribute ok=true in the same convergent loop
    // (R7/R13 proven shape: single loop, single __all_sync site).
    const int  cidx    = warp * 64 + lane * 2;
    const bool pactive = cidx < DIM;
    const unsigned long long* const pb0 = &g_xp[0][pactive ? cidx : 0];
    const unsigned long long* const pb1 = &g_xp[1][pactive ? cidx : 0];

    __syncthreads();
    float xold = 0.0f;

    for (int s = 0; s < TLEN; ++s) {
        const float u_s = __ldg(u + s);

        // ---- poll own chunk: tag+data arrive in the same load (R13 loop) ----
        if (s > 0) {
            const unsigned tgt = base + (unsigned)s;
            const unsigned long long* pb = ((s - 1) & 1) ? pb1 : pb0;
            float f0 = 0.f, f1 = 0.f;
            for (;;) {                       // ONE convergent loop, all lanes
                bool ok = true;
                if (pactive) {
                    ulonglong2 q0 = ld_cv2(pb);
                    unsigned v0, t0, v1, t1;
                    unpk(q0.x, v0, t0); unpk(q0.y, v1, t1);
                    f0 = __uint_as_float(v0); f1 = __uint_as_float(v1);
                    ok = (t0 == tgt) & (t1 == tgt);
                }
                if (__all_sync(0xffffffffu, ok)) break;
            }
            if (pactive)
                *(float2*)(x_sm + cidx) = make_float2(f0, f1);
        }
        __syncthreads();   // bar1: x_{s-1} fully staged (BAR drains STS)

        // ---- compute this warp's 2 rows from smem ----
        unsigned long long acc[2][2] = {};
        if (s > 0) {
            #pragma unroll
            for (int k = 0; k < 8; ++k) {
                ulonglong2 xv = *(const ulonglong2*)(x_sm + k * 128 + lane * 4);
                fma2(acc[0][0], wp[0][k][0], xv.x);
                fma2(acc[0][1], wp[0][k][1], xv.y);
                fma2(acc[1][0], wp[1][k][0], xv.x);
                fma2(acc[1][1], wp[1][k][1], xv.y);
            }
        }
        float s0 = sum2(acc[0][0]) + sum2(acc[0][1]);
        float s1 = sum2(acc[1][0]) + sum2(acc[1][1]);
        // Pre-fold input-drive injection (lane 0 -> row0, lane 16 -> row1):
        // removes one dependent FFMA from the post-fold critical path.
        if (winj) { if (myg == 0) s0 += winv * u_s; else s1 += winv * u_s; }

        // ---- packed f32x2 butterfly fold: both rows reduced simultaneously.
        // 5 levels; each = one 64b shfl (2 back-to-back SHFLs) + add.rn.f32x2.
        unsigned long long pv = pk2(s0, s1);
        #pragma unroll
        for (int off = 16; off > 0; off >>= 1)
            pv = add2(pv, __shfl_xor_sync(0xffffffffu, pv, off));
        float rlo, rhi;
        unpkf(pv, rlo, rhi);                     // lo = row0 sum, hi = row1 sum
        const float v = (myg == 0) ? rlo : rhi;

        const float xn = 0.3f * xold + 0.7f * ftanh(v);
        xold = xn;

        // ---- publish: one atomic 8B {value, tag} store per row, no fence ----
        if (vrow && winj) {
            st_cg64(&g_xp[s & 1][myrow], pk_pair(xn, base + (unsigned)s + 1u));
            if (s > DISCARD)
                out[(size_t)myrow * OUTCOLS + (s - (DISCARD + 1))] = xn;
        }

        __syncthreads();   // bar2: keeps warps phase-locked (R14 proved it pays)
    }
}

extern "C" void kernel_launch(void* const* d_in, const int* in_sizes, int n_in,
                              void* d_out, int out_size) {
    const float* W   = (const float*)d_in[0];
    const float* Win = (const float*)d_in[1];
    const float* u   = (const float*)d_in[2];
    esn_persistent<<<NCTA, NTHREADS>>>(W, Win, u, (float*)d_out);
}

// round 17
// speedup vs baseline: 1.3684x; 1.3684x over previous
#include <cuda_runtime.h>
#include <cstdint>
#include <cstddef>

#define DIM      900
#define TLEN     31000
#define DISCARD  1000
#define OUTCOLS  29999      /* TLEN - DISCARD - 1 */
#define NCTA     30
#define RPC      30         /* rows per CTA */
#define NTHREADS 512        /* 16 warps; warps 0-14: 2 rows, warp 15: 0 rows */
#define PADDIM   1024

// Broadcast state: 900 self-verifying 8B words {f32 value (lo), u32 tag (hi)},
// ping-pong by step parity. 64-bit aligned stores are single-copy atomic: a
// fresh tag ALWAYS travels with its fresh value — no fences, no flags.
// Lap safety: a row's tag on parity p advances +2 only after every CTA's poll
// warps consumed the previous tag on that parity (bar1 couples all 16 chunks
// of a CTA => all 900 rows). Tags grow monotonically across graph replays;
// base is recovered from g_xp[1][0], which cannot be overwritten before all
// warps read it (overwrite needs a step-1 publish => all step-0 publishes =>
// all base reads done).
//
// HARD-WON RULE (R1/R2, R16): the spin MUST be the warp-voted form — all
// lanes reload until the ENTIRE warp sees fresh tags, data taken from the
// final pass. Per-lane early-exit spins return stale data on this chip.
__device__ __align__(16) unsigned long long g_xp[2][PADDIM];

__device__ __forceinline__ ulonglong2 ld_cv2(const unsigned long long* p) {
    ulonglong2 v;
    asm volatile("ld.global.cv.v2.b64 {%0,%1}, [%2];"
                 : "=l"(v.x), "=l"(v.y) : "l"(p) : "memory");
    return v;
}
__device__ __forceinline__ void st_cg64(unsigned long long* p, unsigned long long v) {
    asm volatile("st.global.cg.b64 [%0], %1;" :: "l"(p), "l"(v) : "memory");
}
__device__ __forceinline__ unsigned long long pk_pair(float v, unsigned tag) {
    unsigned long long r;
    asm("mov.b64 %0, {%1,%2};" : "=l"(r) : "r"(__float_as_uint(v)), "r"(tag));
    return r;
}
__device__ __forceinline__ void unpk(unsigned long long w, unsigned& lo, unsigned& hi) {
    asm("mov.b64 {%0,%1}, %2;" : "=r"(lo), "=r"(hi) : "l"(w));
}
__device__ __forceinline__ unsigned long long pk2(float a, float b) {
    unsigned long long r;
    asm("mov.b64 %0, {%1,%2};" : "=l"(r) : "f"(a), "f"(b));
    return r;
}
// Packed dual fp32 FMA (B300 FFMA2) — exact fp32 semantics, 2 MACs/instr.
__device__ __forceinline__ void fma2(unsigned long long& acc,
                                     unsigned long long a, unsigned long long b) {
    asm("fma.rn.f32x2 %0, %1, %2, %0;" : "+l"(acc) : "l"(a), "l"(b));
}
__device__ __forceinline__ float sum2(unsigned long long a) {
    float lo, hi;
    asm("mov.b64 {%0,%1}, %2;" : "=f"(lo), "=f"(hi) : "l"(a));
    return lo + hi;
}
// Fast tanh: 1 - 2/(exp(2x)+1). MUFU-based; ~1e-7 abs error.
__device__ __forceinline__ float ftanh(float x) {
    float e = __expf(2.0f * x);
    return 1.0f - __fdividef(2.0f, e + 1.0f);
}

__global__ void __launch_bounds__(NTHREADS, 1) esn_persistent(
    const float* __restrict__ W,     // (900, 900) row-major, symmetric
    const float* __restrict__ Win,   // (900, 900) row-major; column 0 used
    const float* __restrict__ u,     // (31000,)
    float* __restrict__ out)         // (900, 29999) row-major
{
    __shared__ __align__(16) float x_sm[PADDIM];   // single buffer, 2 bars (R13)

    const int tid  = threadIdx.x;
    const int cta  = blockIdx.x;
    const int warp = tid >> 5;
    const int lane = tid & 31;

    // Zero x_sm; pad region [900,1024) stays zero forever.
    for (int i = tid; i < PADDIM; i += NTHREADS) x_sm[i] = 0.0f;

    // Launch base: tag of row 0, parity 1 (last parity a full launch writes).
    unsigned base;
    { unsigned lo; unpk(ld_cv2(&g_xp[1][0]).x, lo, base); }

    // ---- This warp's 2 rows of W into registers, pre-scaled by 0.9 ----
    const int rbase = cta * RPC + warp * 2;
    unsigned long long wp[2][8][2];
    #pragma unroll
    for (int g = 0; g < 2; ++g) {
        const bool vg = (warp * 2 + g) < RPC;   // warp 15: no rows
        #pragma unroll
        for (int k = 0; k < 8; ++k) {
            const int col = k * 128 + lane * 4;
            float a0 = 0.f, a1 = 0.f, a2 = 0.f, a3 = 0.f;
            if (vg && col + 3 < DIM) {
                float4 v = *(const float4*)(W + (size_t)(rbase + g) * DIM + col);
                a0 = v.x; a1 = v.y; a2 = v.z; a3 = v.w;
            }
            wp[g][k][0] = pk2(0.9f * a0, 0.9f * a1);
            wp[g][k][1] = pk2(0.9f * a2, 0.9f * a3);
        }
    }
    const int  myg   = lane >> 4;                  // 0: lanes 0-15, 1: 16-31
    const bool vrow  = (warp * 2 + myg) < RPC;
    const int  myrow = rbase + myg;
    const float winv = vrow ? Win[(size_t)myrow * DIM] : 0.0f;   // W_in[row,0]
    const bool winj  = ((lane & 15) == 0);   // lanes 0 / 16 inject + publish

    // Poll chunk: pairs [warp*64 + lane*2, +2) — ONE 16B load per lane.
    // Warps 0-13 fully active; warp 14: lanes 0-1; warp 15: inactive.
    // Inactive lanes contribute ok=true in the same convergent loop.
    const int  cidx    = warp * 64 + lane * 2;
    const bool pactive = cidx < DIM;
    const unsigned long long* const pb0 = &g_xp[0][pactive ? cidx : 0];
    const unsigned long long* const pb1 = &g_xp[1][pactive ? cidx : 0];

    __syncthreads();
    float xold = 0.0f;

    for (int s = 0; s < TLEN; ++s) {
        const float u_s = __ldg(u + s);

        // ---- WARP-VOTED spin (mandatory form — see rule above) ----
        if (s > 0) {
            const unsigned tgt = base + (unsigned)s;
            const unsigned long long* pb = ((s - 1) & 1) ? pb1 : pb0;
            float f0 = 0.f, f1 = 0.f;
            for (;;) {                       // ONE convergent loop, all lanes
                bool ok = true;
                if (pactive) {
                    ulonglong2 q0 = ld_cv2(pb);
                    unsigned v0, t0, v1, t1;
                    unpk(q0.x, v0, t0); unpk(q0.y, v1, t1);
                    f0 = __uint_as_float(v0); f1 = __uint_as_float(v1);
                    ok = (t0 == tgt) & (t1 == tgt);
                }
                if (__all_sync(0xffffffffu, ok)) break;
            }
            if (pactive)
                *(float2*)(x_sm + cidx) = make_float2(f0, f1);
        }
        __syncthreads();   // bar1: x_{s-1} fully staged (BAR drains STS)

        // ---- compute this warp's 2 rows from smem (identical to R13) ----
        unsigned long long acc[2][2] = {};
        if (s > 0) {
            #pragma unroll
            for (int k = 0; k < 8; ++k) {
                ulonglong2 xv = *(const ulonglong2*)(x_sm + k * 128 + lane * 4);
                fma2(acc[0][0], wp[0][k][0], xv.x);
                fma2(acc[0][1], wp[0][k][1], xv.y);
                fma2(acc[1][0], wp[1][k][0], xv.x);
                fma2(acc[1][1], wp[1][k][1], xv.y);
            }
        }
        float s0 = sum2(acc[0][0]) + sum2(acc[0][1]);
        float s1 = sum2(acc[1][0]) + sum2(acc[1][1]);
        // Pre-fold input-drive injection (lane 0 -> row0, lane 16 -> row1):
        // removes one dependent FFMA from the post-fold critical tail.
        if (winj) { if (myg == 0) s0 += winv * u_s; else s1 += winv * u_s; }

        // Merged fold (R13): lanes 0-15 end with full row0 sum, 16-31 row1.
        float va = (lane & 16) ? s1 : s0;
        float vb = (lane & 16) ? s0 : s1;
        va += __shfl_xor_sync(0xffffffffu, vb, 16);
        va += __shfl_xor_sync(0xffffffffu, va, 8);
        va += __shfl_xor_sync(0xffffffffu, va, 4);
        va += __shfl_xor_sync(0xffffffffu, va, 2);
        va += __shfl_xor_sync(0xffffffffu, va, 1);

        const float xn = 0.3f * xold + 0.7f * ftanh(va);
        xold = xn;

        // ---- publish: one atomic 8B {value, tag} store per row, no fence ----
        if (vrow && winj) {
            st_cg64(&g_xp[s & 1][myrow], pk_pair(xn, base + (unsigned)s + 1u));
            if (s > DISCARD)
                out[(size_t)myrow * OUTCOLS + (s - (DISCARD + 1))] = xn;
        }

        __syncthreads();   // bar2: keeps warps phase-locked (R14 proved it pays)
    }
}

extern "C" void kernel_launch(void* const* d_in, const int* in_sizes, int n_in,
                              void* d_out, int out_size) {
    const float* W   = (const float*)d_in[0];
    const float* Win = (const float*)d_in[1];
    const float* u   = (const float*)d_in[2];
    esn_persistent<<<NCTA, NTHREADS>>>(W, Win, u, (float*)d_out);
}